// round 12
// baseline (speedup 1.0000x reference)
#include <cuda_runtime.h>
#include <cuda_fp16.h>
#include <cstdint>

constexpr int NROWS  = 65536;
constexpr int DFEAT  = 32;
constexpr int H      = 128;
constexpr int NJ     = H + 1;          // 129 intervals
constexpr int SPLITS = 32;
constexpr int RPB    = NROWS / SPLITS; // 2048 rows per main CTA

// persistent scratch (static device globals — no runtime allocation)
// per (d, j, lane): uint4 {P01, P23, Q01, Q23} covering k = 4*lane .. 4*lane+3
__device__ uint4 g_tab4[DFEAT][NJ][32];
__device__ float g_kn  [DFEAT][H];

__device__ __forceinline__ uint32_t h2u(__half2 h) {
    return *reinterpret_cast<uint32_t*>(&h);
}
__device__ __forceinline__ __half2 u2h(uint32_t u) {
    return *reinterpret_cast<__half2*>(&u);
}

// ---------------- precompute: incremental interval tables ----------------
// one CTA per feature d; 128 threads. Warp w builds interval range
// [j0_w, jend_w] via midpoint init + one-knee-flip incremental updates.
constexpr int PRE_SMEM = (H * H + 7 * H) * 4;   // W2 + 7 small arrays

__global__ void __launch_bounds__(128)
kan_precompute(const float* __restrict__ W1, const float* __restrict__ b1,
               const float* __restrict__ W2, const float* __restrict__ b2)
{
    extern __shared__ float ps[];
    float* W2s = ps;               // 16384
    float* w1s = W2s + H * H;      // 128
    float* b1s = w1s + H;
    float* b2s = b1s + H;
    float* kns = b2s + H;          // sorted knees
    float* sus = kns + H;          // |w1_c| in knee-sorted order
    float* svs = sus + H;          // sign(w1_c)*b1_c in knee-sorted order
    int*   cix = reinterpret_cast<int*>(svs + H);  // unit index per rank

    const int d = blockIdx.x, tid = threadIdx.x;

    const float* w2d = W2 + (size_t)d * H * H;
    for (int i = tid; i < H * H / 4; i += 128)
        reinterpret_cast<float4*>(W2s)[i] =
            reinterpret_cast<const float4*>(w2d)[i];
    w1s[tid] = W1[d * H + tid];
    b1s[tid] = b1[d * H + tid];
    b2s[tid] = b2[d * H + tid];
    __syncthreads();

    // knee + exact rank sort (thread = unit)
    {
        const float w = w1s[tid], bb = b1s[tid];
        const float t = (w != 0.f) ? (-bb / w) : 3.0e38f;
        int rank = 0;
        for (int c = 0; c < H; ++c) {
            const float wc = w1s[c], bc = b1s[c];
            const float tc = (wc != 0.f) ? (-bc / wc) : 3.0e38f;
            rank += (tc < t) || ((tc == t) && (c < tid));
        }
        kns[rank] = t;
        cix[rank] = tid;
        sus[rank] = fabsf(w);
        svs[rank] = (w > 0.f) ? bb : -bb;   // sign(w)*b1 (w==0 never crossed)
    }
    __syncthreads();
    g_kn[d][tid] = kns[tid];

    const int warp = tid >> 5, lane = tid & 31;
    const int j0   = (warp == 0) ? 0 : warp * 32 + 1;
    const int jend = warp * 32 + 32;       // warp0: 0..32, w: 32w+1..32w+32
    const int kb   = lane * 4;

    // midpoint of interval j0 (overflow-safe form)
    float m;
    if (j0 == 0) m = kns[0] - 1.0f;
    else         m = kns[j0 - 1] + 0.5f * (kns[j0] - kns[j0 - 1]);

    float P[4] = {0.f, 0.f, 0.f, 0.f};
    float Q[4] = {b2s[kb], b2s[kb + 1], b2s[kb + 2], b2s[kb + 3]};
    for (int c = 0; c < H; ++c) {
        const float wc = w1s[c], bc = b1s[c];
        if (m * wc + bc > 0.f) {
            const float4 wv = *reinterpret_cast<const float4*>(W2s + c * H + kb);
            P[0] = fmaf(wc, wv.x, P[0]); Q[0] = fmaf(bc, wv.x, Q[0]);
            P[1] = fmaf(wc, wv.y, P[1]); Q[1] = fmaf(bc, wv.y, Q[1]);
            P[2] = fmaf(wc, wv.z, P[2]); Q[2] = fmaf(bc, wv.z, Q[2]);
            P[3] = fmaf(wc, wv.w, P[3]); Q[3] = fmaf(bc, wv.w, Q[3]);
        }
    }
    auto store = [&](int j) {
        uint4 u;
        u.x = h2u(__floats2half2_rn(P[0], P[1]));
        u.y = h2u(__floats2half2_rn(P[2], P[3]));
        u.z = h2u(__floats2half2_rn(Q[0], Q[1]));
        u.w = h2u(__floats2half2_rn(Q[2], Q[3]));
        g_tab4[d][j][lane] = u;
    };
    store(j0);
    for (int j = j0 + 1; j <= jend; ++j) {
        const int   c  = cix[j - 1];
        const float uu = sus[j - 1], vv = svs[j - 1];
        const float4 wv = *reinterpret_cast<const float4*>(W2s + c * H + kb);
        P[0] = fmaf(uu, wv.x, P[0]); Q[0] = fmaf(vv, wv.x, Q[0]);
        P[1] = fmaf(uu, wv.y, P[1]); Q[1] = fmaf(vv, wv.y, Q[1]);
        P[2] = fmaf(uu, wv.z, P[2]); Q[2] = fmaf(vv, wv.z, Q[2]);
        P[3] = fmaf(uu, wv.w, P[3]); Q[3] = fmaf(vv, wv.w, Q[3]);
        store(j);
    }
}

// ---------------- main: interval lookup + half2-native evaluation ----------
// SMEM floats: tab4 16512 | kns 128 | trans 8448 | stage 512 = 25600 (100 KB)
constexpr int SM_TAB    = 0;
constexpr int SM_KN     = NJ * 32 * 4;            // 16512 u32
constexpr int SM_TR     = SM_KN + H;              // 16640
constexpr int SM_ST     = SM_TR + 8 * 32 * 33;    // 25088
constexpr int SM_FLOATS = SM_ST + 8 * 32 * 2;     // 25600
constexpr int MAIN_SMEM = SM_FLOATS * 4;          // 102400 B (x2 = 200 KB)

__global__ void __launch_bounds__(256, 2)
kan_main(const float* __restrict__ x, const float* __restrict__ W3,
         const float* __restrict__ b3, float* __restrict__ out)
{
    extern __shared__ float s[];
    uint4* tab4 = reinterpret_cast<uint4*>(s + SM_TAB);
    float* kns  = s + SM_KN;
    float* tran = s + SM_TR;
    uint2* stg  = reinterpret_cast<uint2*>(s + SM_ST);

    const int tid   = threadIdx.x;
    const int d     = blockIdx.x & (DFEAT - 1);  // d fastest -> x L2 reuse
    const int split = blockIdx.x >> 5;
    const int n0    = split * RPB;
    const int lane  = tid & 31, w = tid >> 5;

    // load this feature's packed table + knees into SMEM
    {
        const uint4* src = &g_tab4[d][0][0];
        for (int i = tid; i < NJ * 32; i += 256) tab4[i] = src[i];
        for (int i = tid; i < H; i += 256) kns[i] = g_kn[d][i];
    }
    __syncthreads();

    // per-lane W3 pairs (half2) for k = 4*lane .. 4*lane+3
    const float4 w3f = reinterpret_cast<const float4*>(W3 + d * H)[lane];
    const __half2 w301 = __floats2half2_rn(w3f.x, w3f.y);
    const __half2 w323 = __floats2half2_rn(w3f.z, w3f.w);
    const float   b3d  = b3[d];
    const __half2 zero2 = __float2half2_rn(0.f);

    float* tr = tran + w * (32 * 33);
    uint2* st = stg + w * 32;

    for (int b = 0; b < RPB / 256; ++b) {     // 8 batches of 32 rows per warp
        const int rowb = n0 + (b * 8 + w) * 32;

        // each lane owns one row: load x, locate interval (binary count)
        const float xv = x[(size_t)(rowb + lane) * DFEAT + d];
        int j = 0;
        #pragma unroll
        for (int stp = 128; stp > 0; stp >>= 1)
            if (j + stp <= H && kns[j + stp - 1] <= xv) j += stp;

        // stage packed x (half2) and uint4-offset for warp-broadcast reads
        st[lane] = make_uint2(h2u(__half2half2(__float2half_rn(xv))),
                              (uint32_t)(j * 32));
        __syncwarp();

        // per row r, lanes cover 128 k's (4 each, half2-native)
        #pragma unroll 4
        for (int r = 0; r < 32; ++r) {
            const uint2 sv = st[r];
            const __half2 x2 = u2h(sv.x);
            const uint4 pv = tab4[sv.y + lane];
            const __half2 h01 = __hmax2(__hfma2(x2, u2h(pv.x), u2h(pv.z)), zero2);
            const __half2 h23 = __hmax2(__hfma2(x2, u2h(pv.y), u2h(pv.w)), zero2);
            const __half2 pr2 = __hfma2(h01, w301, __hmul2(h23, w323));
            const float2  pf  = __half22float2(pr2);
            tr[r * 33 + lane] = pf.x + pf.y;   // partial of row r by this lane
        }
        __syncwarp();

        // lane L reduces row L (conflict-free: stride 33)
        float sum = b3d;
        #pragma unroll
        for (int i = 0; i < 32; ++i) sum += tr[lane * 33 + i];
        atomicAdd(out + rowb + lane, sum);
        __syncwarp();                          // protect tr/st before next batch
    }
}

extern "C" void kernel_launch(void* const* d_in, const int* in_sizes, int n_in,
                              void* d_out, int out_size) {
    const float* x  = (const float*)d_in[0];
    const float* W1 = (const float*)d_in[1];
    const float* b1 = (const float*)d_in[2];
    const float* W2 = (const float*)d_in[3];
    const float* b2 = (const float*)d_in[4];
    const float* W3 = (const float*)d_in[5];
    const float* b3 = (const float*)d_in[6];
    float* out = (float*)d_out;

    cudaFuncSetAttribute(kan_precompute,
                         cudaFuncAttributeMaxDynamicSharedMemorySize, PRE_SMEM);
    cudaFuncSetAttribute(kan_main,
                         cudaFuncAttributeMaxDynamicSharedMemorySize, MAIN_SMEM);

    cudaMemsetAsync(d_out, 0, (size_t)out_size * sizeof(float), 0);
    kan_precompute<<<DFEAT, 128, PRE_SMEM>>>(W1, b1, W2, b2);
    kan_main<<<DFEAT * SPLITS, 256, MAIN_SMEM>>>(x, W3, b3, out);
}

// round 13
// speedup vs baseline: 1.0021x; 1.0021x over previous
#include <cuda_runtime.h>
#include <cuda_fp16.h>
#include <cstdint>

constexpr int NROWS  = 65536;
constexpr int DFEAT  = 32;
constexpr int H      = 128;
constexpr int NJ     = H + 1;          // 129 intervals
constexpr int SPLITS = 32;
constexpr int RPB    = NROWS / SPLITS; // 2048 rows per main CTA

// persistent scratch (static device globals — no runtime allocation)
// per (d, j, lane): uint4 {P01, P23, Q01, Q23} covering k = 4*lane .. 4*lane+3
__device__ uint4 g_tab4[DFEAT][NJ][32];
__device__ float g_kn  [DFEAT][H];

__device__ __forceinline__ uint32_t h2u(__half2 h) {
    return *reinterpret_cast<uint32_t*>(&h);
}
__device__ __forceinline__ __half2 u2h(uint32_t u) {
    return *reinterpret_cast<__half2*>(&u);
}

// ---------------- precompute: incremental interval tables ----------------
// one CTA per feature d; 128 threads. Warp w builds interval range
// [j0_w, jend_w] via midpoint init + one-knee-flip incremental updates.
constexpr int PRE_SMEM = (H * H + 7 * H) * 4;   // W2 + 7 small arrays

__global__ void __launch_bounds__(128)
kan_precompute(const float* __restrict__ W1, const float* __restrict__ b1,
               const float* __restrict__ W2, const float* __restrict__ b2)
{
    extern __shared__ float ps[];
    float* W2s = ps;               // 16384
    float* w1s = W2s + H * H;      // 128
    float* b1s = w1s + H;
    float* b2s = b1s + H;
    float* kns = b2s + H;          // sorted knees
    float* sus = kns + H;          // |w1_c| in knee-sorted order
    float* svs = sus + H;          // sign(w1_c)*b1_c in knee-sorted order
    int*   cix = reinterpret_cast<int*>(svs + H);  // unit index per rank

    const int d = blockIdx.x, tid = threadIdx.x;

    const float* w2d = W2 + (size_t)d * H * H;
    for (int i = tid; i < H * H / 4; i += 128)
        reinterpret_cast<float4*>(W2s)[i] =
            reinterpret_cast<const float4*>(w2d)[i];
    w1s[tid] = W1[d * H + tid];
    b1s[tid] = b1[d * H + tid];
    b2s[tid] = b2[d * H + tid];
    __syncthreads();

    // knee + exact rank sort (thread = unit)
    {
        const float w = w1s[tid], bb = b1s[tid];
        const float t = (w != 0.f) ? (-bb / w) : 3.0e38f;
        int rank = 0;
        for (int c = 0; c < H; ++c) {
            const float wc = w1s[c], bc = b1s[c];
            const float tc = (wc != 0.f) ? (-bc / wc) : 3.0e38f;
            rank += (tc < t) || ((tc == t) && (c < tid));
        }
        kns[rank] = t;
        cix[rank] = tid;
        sus[rank] = fabsf(w);
        svs[rank] = (w > 0.f) ? bb : -bb;   // sign(w)*b1 (w==0 never crossed)
    }
    __syncthreads();
    g_kn[d][tid] = kns[tid];

    const int warp = tid >> 5, lane = tid & 31;
    const int j0   = (warp == 0) ? 0 : warp * 32 + 1;
    const int jend = warp * 32 + 32;       // warp0: 0..32, w: 32w+1..32w+32
    const int kb   = lane * 4;

    // midpoint of interval j0 (overflow-safe form)
    float m;
    if (j0 == 0) m = kns[0] - 1.0f;
    else         m = kns[j0 - 1] + 0.5f * (kns[j0] - kns[j0 - 1]);

    float P[4] = {0.f, 0.f, 0.f, 0.f};
    float Q[4] = {b2s[kb], b2s[kb + 1], b2s[kb + 2], b2s[kb + 3]};
    for (int c = 0; c < H; ++c) {
        const float wc = w1s[c], bc = b1s[c];
        if (m * wc + bc > 0.f) {
            const float4 wv = *reinterpret_cast<const float4*>(W2s + c * H + kb);
            P[0] = fmaf(wc, wv.x, P[0]); Q[0] = fmaf(bc, wv.x, Q[0]);
            P[1] = fmaf(wc, wv.y, P[1]); Q[1] = fmaf(bc, wv.y, Q[1]);
            P[2] = fmaf(wc, wv.z, P[2]); Q[2] = fmaf(bc, wv.z, Q[2]);
            P[3] = fmaf(wc, wv.w, P[3]); Q[3] = fmaf(bc, wv.w, Q[3]);
        }
    }
    auto store = [&](int j) {
        uint4 u;
        u.x = h2u(__floats2half2_rn(P[0], P[1]));
        u.y = h2u(__floats2half2_rn(P[2], P[3]));
        u.z = h2u(__floats2half2_rn(Q[0], Q[1]));
        u.w = h2u(__floats2half2_rn(Q[2], Q[3]));
        g_tab4[d][j][lane] = u;
    };
    store(j0);
    for (int j = j0 + 1; j <= jend; ++j) {
        const int   c  = cix[j - 1];
        const float uu = sus[j - 1], vv = svs[j - 1];
        const float4 wv = *reinterpret_cast<const float4*>(W2s + c * H + kb);
        P[0] = fmaf(uu, wv.x, P[0]); Q[0] = fmaf(vv, wv.x, Q[0]);
        P[1] = fmaf(uu, wv.y, P[1]); Q[1] = fmaf(vv, wv.y, Q[1]);
        P[2] = fmaf(uu, wv.z, P[2]); Q[2] = fmaf(vv, wv.z, Q[2]);
        P[3] = fmaf(uu, wv.w, P[3]); Q[3] = fmaf(vv, wv.w, Q[3]);
        store(j);
    }
}

// ---------------- main: interval lookup + half2-native evaluation ----------
// SMEM floats: tab4 16512 | kns 128 | trans 8448 | stage 512 = 25600 (100 KB)
constexpr int SM_TAB    = 0;
constexpr int SM_KN     = NJ * 32 * 4;            // 16512 u32
constexpr int SM_TR     = SM_KN + H;              // 16640
constexpr int SM_ST     = SM_TR + 8 * 32 * 33;    // 25088
constexpr int SM_FLOATS = SM_ST + 8 * 32 * 2;     // 25600
constexpr int MAIN_SMEM = SM_FLOATS * 4;          // 102400 B (x2 = 200 KB)

__global__ void __launch_bounds__(256, 2)
kan_main(const float* __restrict__ x, const float* __restrict__ W3,
         const float* __restrict__ b3, float* __restrict__ out)
{
    extern __shared__ float s[];
    uint4* tab4 = reinterpret_cast<uint4*>(s + SM_TAB);
    float* kns  = s + SM_KN;
    float* tran = s + SM_TR;
    uint2* stg  = reinterpret_cast<uint2*>(s + SM_ST);

    const int tid   = threadIdx.x;
    const int d     = blockIdx.x & (DFEAT - 1);  // d fastest -> x L2 reuse
    const int split = blockIdx.x >> 5;
    const int n0    = split * RPB;
    const int lane  = tid & 31, w = tid >> 5;

    // load this feature's packed table + knees into SMEM
    {
        const uint4* src = &g_tab4[d][0][0];
        for (int i = tid; i < NJ * 32; i += 256) tab4[i] = src[i];
        for (int i = tid; i < H; i += 256) kns[i] = g_kn[d][i];
    }
    __syncthreads();

    // per-lane W3 pairs (half2) for k = 4*lane .. 4*lane+3
    const float4 w3f = reinterpret_cast<const float4*>(W3 + d * H)[lane];
    const __half2 w301 = __floats2half2_rn(w3f.x, w3f.y);
    const __half2 w323 = __floats2half2_rn(w3f.z, w3f.w);
    const float   b3d  = b3[d];
    const __half2 zero2 = __float2half2_rn(0.f);

    float* tr = tran + w * (32 * 33);
    uint2* st = stg + w * 32;

    for (int b = 0; b < RPB / 256; ++b) {     // 8 batches of 32 rows per warp
        const int rowb = n0 + (b * 8 + w) * 32;

        // each lane owns one row: load x, locate interval (binary count)
        const float xv = x[(size_t)(rowb + lane) * DFEAT + d];
        int j = 0;
        #pragma unroll
        for (int stp = 128; stp > 0; stp >>= 1)
            if (j + stp <= H && kns[j + stp - 1] <= xv) j += stp;

        // stage packed x (half2) and uint4-offset for warp-broadcast reads
        st[lane] = make_uint2(h2u(__half2half2(__float2half_rn(xv))),
                              (uint32_t)(j * 32));
        __syncwarp();

        // per row r, lanes cover 128 k's (4 each, half2-native)
        #pragma unroll 4
        for (int r = 0; r < 32; ++r) {
            const uint2 sv = st[r];
            const __half2 x2 = u2h(sv.x);
            const uint4 pv = tab4[sv.y + lane];
            const __half2 h01 = __hmax2(__hfma2(x2, u2h(pv.x), u2h(pv.z)), zero2);
            const __half2 h23 = __hmax2(__hfma2(x2, u2h(pv.y), u2h(pv.w)), zero2);
            const __half2 pr2 = __hfma2(h01, w301, __hmul2(h23, w323));
            const float2  pf  = __half22float2(pr2);
            tr[r * 33 + lane] = pf.x + pf.y;   // partial of row r by this lane
        }
        __syncwarp();

        // lane L reduces row L (conflict-free: stride 33)
        float sum = b3d;
        #pragma unroll
        for (int i = 0; i < 32; ++i) sum += tr[lane * 33 + i];
        atomicAdd(out + rowb + lane, sum);
        __syncwarp();                          // protect tr/st before next batch
    }
}

extern "C" void kernel_launch(void* const* d_in, const int* in_sizes, int n_in,
                              void* d_out, int out_size) {
    const float* x  = (const float*)d_in[0];
    const float* W1 = (const float*)d_in[1];
    const float* b1 = (const float*)d_in[2];
    const float* W2 = (const float*)d_in[3];
    const float* b2 = (const float*)d_in[4];
    const float* W3 = (const float*)d_in[5];
    const float* b3 = (const float*)d_in[6];
    float* out = (float*)d_out;

    cudaFuncSetAttribute(kan_precompute,
                         cudaFuncAttributeMaxDynamicSharedMemorySize, PRE_SMEM);
    cudaFuncSetAttribute(kan_main,
                         cudaFuncAttributeMaxDynamicSharedMemorySize, MAIN_SMEM);

    cudaMemsetAsync(d_out, 0, (size_t)out_size * sizeof(float), 0);
    kan_precompute<<<DFEAT, 128, PRE_SMEM>>>(W1, b1, W2, b2);
    kan_main<<<DFEAT * SPLITS, 256, MAIN_SMEM>>>(x, W3, b3, out);
}

// round 14
// speedup vs baseline: 1.2409x; 1.2382x over previous
#include <cuda_runtime.h>
#include <cuda_fp16.h>
#include <cstdint>

constexpr int NROWS  = 65536;
constexpr int DFEAT  = 32;
constexpr int H      = 128;
constexpr int NJ     = H + 1;          // 129 intervals
constexpr int SPLITS = 64;
constexpr int RPB    = NROWS / SPLITS; // 1024 rows per main CTA

// persistent scratch (static device globals — no runtime allocation)
// per (d, j, chunk): uint4 {P01, P23, Q01, Q23} covering k = 4*chunk..4*chunk+3
__device__ uint4 g_tab4[DFEAT][NJ][32];
__device__ float g_kn  [DFEAT][H];

__device__ __forceinline__ uint32_t h2u(__half2 h) {
    return *reinterpret_cast<uint32_t*>(&h);
}
__device__ __forceinline__ __half2 u2h(uint32_t u) {
    return *reinterpret_cast<__half2*>(&u);
}

// ---------------- precompute: incremental interval tables ----------------
constexpr int PRE_SMEM = (H * H + 7 * H) * 4;

__global__ void __launch_bounds__(128)
kan_precompute(const float* __restrict__ W1, const float* __restrict__ b1,
               const float* __restrict__ W2, const float* __restrict__ b2)
{
    extern __shared__ float ps[];
    float* W2s = ps;               // 16384
    float* w1s = W2s + H * H;      // 128
    float* b1s = w1s + H;
    float* b2s = b1s + H;
    float* kns = b2s + H;          // sorted knees
    float* sus = kns + H;          // |w1_c| in knee order
    float* svs = sus + H;          // sign(w1_c)*b1_c in knee order
    int*   cix = reinterpret_cast<int*>(svs + H);

    const int d = blockIdx.x, tid = threadIdx.x;

    const float* w2d = W2 + (size_t)d * H * H;
    for (int i = tid; i < H * H / 4; i += 128)
        reinterpret_cast<float4*>(W2s)[i] =
            reinterpret_cast<const float4*>(w2d)[i];
    w1s[tid] = W1[d * H + tid];
    b1s[tid] = b1[d * H + tid];
    b2s[tid] = b2[d * H + tid];
    __syncthreads();

    // knee + exact rank sort (thread = unit)
    {
        const float w = w1s[tid], bb = b1s[tid];
        const float t = (w != 0.f) ? (-bb / w) : 3.0e38f;
        int rank = 0;
        for (int c = 0; c < H; ++c) {
            const float wc = w1s[c], bc = b1s[c];
            const float tc = (wc != 0.f) ? (-bc / wc) : 3.0e38f;
            rank += (tc < t) || ((tc == t) && (c < tid));
        }
        kns[rank] = t;
        cix[rank] = tid;
        sus[rank] = fabsf(w);
        svs[rank] = (w > 0.f) ? bb : -bb;
    }
    __syncthreads();
    g_kn[d][tid] = kns[tid];

    const int warp = tid >> 5, lane = tid & 31;
    const int j0   = (warp == 0) ? 0 : warp * 32 + 1;
    const int jend = warp * 32 + 32;
    const int kb   = lane * 4;

    float m;
    if (j0 == 0) m = kns[0] - 1.0f;
    else         m = kns[j0 - 1] + 0.5f * (kns[j0] - kns[j0 - 1]);

    float P[4] = {0.f, 0.f, 0.f, 0.f};
    float Q[4] = {b2s[kb], b2s[kb + 1], b2s[kb + 2], b2s[kb + 3]};
    for (int c = 0; c < H; ++c) {
        const float wc = w1s[c], bc = b1s[c];
        if (m * wc + bc > 0.f) {
            const float4 wv = *reinterpret_cast<const float4*>(W2s + c * H + kb);
            P[0] = fmaf(wc, wv.x, P[0]); Q[0] = fmaf(bc, wv.x, Q[0]);
            P[1] = fmaf(wc, wv.y, P[1]); Q[1] = fmaf(bc, wv.y, Q[1]);
            P[2] = fmaf(wc, wv.z, P[2]); Q[2] = fmaf(bc, wv.z, Q[2]);
            P[3] = fmaf(wc, wv.w, P[3]); Q[3] = fmaf(bc, wv.w, Q[3]);
        }
    }
    auto store = [&](int j) {
        uint4 u;
        u.x = h2u(__floats2half2_rn(P[0], P[1]));
        u.y = h2u(__floats2half2_rn(P[2], P[3]));
        u.z = h2u(__floats2half2_rn(Q[0], Q[1]));
        u.w = h2u(__floats2half2_rn(Q[2], Q[3]));
        g_tab4[d][j][lane] = u;
    };
    store(j0);
    for (int j = j0 + 1; j <= jend; ++j) {
        const int   c  = cix[j - 1];
        const float uu = sus[j - 1], vv = svs[j - 1];
        const float4 wv = *reinterpret_cast<const float4*>(W2s + c * H + kb);
        P[0] = fmaf(uu, wv.x, P[0]); Q[0] = fmaf(vv, wv.x, Q[0]);
        P[1] = fmaf(uu, wv.y, P[1]); Q[1] = fmaf(vv, wv.y, Q[1]);
        P[2] = fmaf(uu, wv.z, P[2]); Q[2] = fmaf(vv, wv.z, Q[2]);
        P[3] = fmaf(uu, wv.w, P[3]); Q[3] = fmaf(vv, wv.w, Q[3]);
        store(j);
    }
}

// ---------------- main: lane-owns-row, rotated conflict-free reads ---------
// SMEM floats: tab4 16512 (u32) | kns 128 | w3t 64  => 16704 floats = 66816 B
constexpr int SM_KN     = NJ * 32 * 4;            // 16512
constexpr int SM_W3     = SM_KN + H;              // 16640
constexpr int SM_FLOATS = SM_W3 + 64;             // 16704
constexpr int MAIN_SMEM = SM_FLOATS * 4;          // 66816 B (x3 = 196 KB)

__global__ void __launch_bounds__(256, 3)
kan_main(const float* __restrict__ x, const float* __restrict__ W3,
         const float* __restrict__ b3, float* __restrict__ out)
{
    extern __shared__ float s[];
    uint4* tab4 = reinterpret_cast<uint4*>(s);
    float* kns  = s + SM_KN;
    uint2* w3t  = reinterpret_cast<uint2*>(s + SM_W3);

    const int tid   = threadIdx.x;
    const int d     = blockIdx.x & (DFEAT - 1);  // d fastest -> x L2 reuse
    const int split = blockIdx.x >> 5;
    const int n0    = split * RPB;
    const int lane  = tid & 31, w = tid >> 5;

    // prologue: table, knees, w3 pairs
    {
        const uint4* src = &g_tab4[d][0][0];
        for (int i = tid; i < NJ * 32; i += 256) tab4[i] = src[i];
        for (int i = tid; i < H; i += 256) kns[i] = g_kn[d][i];
        if (tid < 32) {
            const float4 wf = reinterpret_cast<const float4*>(W3 + d * H)[tid];
            w3t[tid] = make_uint2(h2u(__floats2half2_rn(wf.x, wf.y)),
                                  h2u(__floats2half2_rn(wf.z, wf.w)));
        }
    }
    __syncthreads();

    const float b3d = b3[d];
    const __half2 zero2 = __float2half2_rn(0.f);

    for (int b = 0; b < RPB / 256; ++b) {     // 4 batches; lane owns a row
        const int row = n0 + (b * 8 + w) * 32 + lane;
        const float xv = x[(size_t)row * DFEAT + d];

        // locate interval (binary count over sorted knees)
        int j = 0;
        #pragma unroll
        for (int stp = 128; stp > 0; stp >>= 1)
            if (j + stp <= H && kns[j + stp - 1] <= xv) j += stp;

        const __half2 x2 = __half2half2(__float2half_rn(xv));
        const int base = j * 32;

        float accA = 0.f, accB = 0.f;
        #pragma unroll
        for (int i = 0; i < 32; ++i) {
            const int c = (i + lane) & 31;     // rotation: conflict-free banks
            const uint4 pv = tab4[base + c];
            const uint2 wv = w3t[c];
            const __half2 h01 = __hmax2(__hfma2(x2, u2h(pv.x), u2h(pv.z)), zero2);
            const __half2 h23 = __hmax2(__hfma2(x2, u2h(pv.y), u2h(pv.w)), zero2);
            const __half2 pr2 = __hfma2(h01, u2h(wv.x), __hmul2(h23, u2h(wv.y)));
            const float2  pf  = __half22float2(pr2);
            accA += pf.x;
            accB += pf.y;
        }
        atomicAdd(out + row, accA + accB + b3d);
    }
}

extern "C" void kernel_launch(void* const* d_in, const int* in_sizes, int n_in,
                              void* d_out, int out_size) {
    const float* x  = (const float*)d_in[0];
    const float* W1 = (const float*)d_in[1];
    const float* b1 = (const float*)d_in[2];
    const float* W2 = (const float*)d_in[3];
    const float* b2 = (const float*)d_in[4];
    const float* W3 = (const float*)d_in[5];
    const float* b3 = (const float*)d_in[6];
    float* out = (float*)d_out;

    cudaFuncSetAttribute(kan_precompute,
                         cudaFuncAttributeMaxDynamicSharedMemorySize, PRE_SMEM);
    cudaFuncSetAttribute(kan_main,
                         cudaFuncAttributeMaxDynamicSharedMemorySize, MAIN_SMEM);

    cudaMemsetAsync(d_out, 0, (size_t)out_size * sizeof(float), 0);
    kan_precompute<<<DFEAT, 128, PRE_SMEM>>>(W1, b1, W2, b2);
    kan_main<<<DFEAT * SPLITS, 256, MAIN_SMEM>>>(x, W3, b3, out);
}